// round 2
// baseline (speedup 1.0000x reference)
#include <cuda_runtime.h>
#include <cuda_bf16.h>
#include <stdint.h>

// Problem constants (fixed by the dataset)
#define NN   2048      // n
#define DD   512       // feature dim
#define CC   128       // classes
#define BB   4096      // 2n
#define TOPK 10

// ---------------- device scratch (no allocations allowed) ----------------
__device__ float g_pd[(size_t)BB * BB];    // 64 MB distance matrix
__device__ float g_feats[(size_t)BB * DD]; // 8 MB packed [z_i; z_j]
__device__ float g_probs[(size_t)BB * CC]; // 2 MB packed [z_i_prob; z_j_prob]
__device__ float g_sq[BB];                 // row squared norms
__device__ float g_partial[BB];            // per-row loss partial sums

// ---------------- pack inputs into contiguous scratch ----------------
__global__ void pack_kernel(const float* __restrict__ zi, const float* __restrict__ zj,
                            const float* __restrict__ pi, const float* __restrict__ pj) {
    const int total_f = NN * DD;  // 1048576
    const int total_p = NN * CC;  // 262144
    for (int i = blockIdx.x * blockDim.x + threadIdx.x; i < total_f;
         i += gridDim.x * blockDim.x) {
        g_feats[i]           = zi[i];
        g_feats[total_f + i] = zj[i];
        if (i < total_p) {
            g_probs[i]           = pi[i];
            g_probs[total_p + i] = pj[i];
        }
    }
}

// ---------------- row squared norms: one warp per row ----------------
__global__ void sqnorm_kernel() {
    int warp = (blockIdx.x * blockDim.x + threadIdx.x) >> 5;
    int lane = threadIdx.x & 31;
    if (warp >= BB) return;
    const float* row = g_feats + (size_t)warp * DD;
    float s = 0.f;
    #pragma unroll
    for (int q = 0; q < 4; q++) {
        float4 v = *(const float4*)(row + (q * 32 + lane) * 4);
        s += v.x * v.x + v.y * v.y + v.z * v.z + v.w * v.w;
    }
    #pragma unroll
    for (int off = 16; off > 0; off >>= 1)
        s += __shfl_down_sync(0xffffffffu, s, off);
    if (lane == 0) g_sq[warp] = s;
}

// ---------------- symmetric distance GEMM: 128x128 tile, 8x8/thread ----------------
__global__ void __launch_bounds__(256, 2) dist_gemm_kernel() {
    const int bi = blockIdx.y, bj = blockIdx.x;
    if (bj < bi) return;  // symmetric: only upper-triangle blocks compute

    __shared__ float As[8][132];
    __shared__ float Bs[8][132];

    const int tid  = threadIdx.x;
    const int tx   = tid & 15;   // 0..15 -> j-octet
    const int ty   = tid >> 4;   // 0..15 -> i-octet
    const int lrow = tid >> 1;   // 0..127 load row
    const int lk4  = (tid & 1) << 2;

    const float* Ap = g_feats + (size_t)(bi * 128 + lrow) * DD + lk4;
    const float* Bp = g_feats + (size_t)(bj * 128 + lrow) * DD + lk4;

    float c[8][8];
    #pragma unroll
    for (int m = 0; m < 8; m++)
        #pragma unroll
        for (int n = 0; n < 8; n++) c[m][n] = 0.f;

    for (int k0 = 0; k0 < DD; k0 += 8) {
        float4 av = *(const float4*)(Ap + k0);
        float4 bv = *(const float4*)(Bp + k0);
        As[lk4 + 0][lrow] = av.x; As[lk4 + 1][lrow] = av.y;
        As[lk4 + 2][lrow] = av.z; As[lk4 + 3][lrow] = av.w;
        Bs[lk4 + 0][lrow] = bv.x; Bs[lk4 + 1][lrow] = bv.y;
        Bs[lk4 + 2][lrow] = bv.z; Bs[lk4 + 3][lrow] = bv.w;
        __syncthreads();
        #pragma unroll
        for (int k = 0; k < 8; k++) {
            float a[8], b[8];
            *(float4*)&a[0] = *(const float4*)&As[k][ty * 8];
            *(float4*)&a[4] = *(const float4*)&As[k][ty * 8 + 4];
            *(float4*)&b[0] = *(const float4*)&Bs[k][tx * 8];
            *(float4*)&b[4] = *(const float4*)&Bs[k][tx * 8 + 4];
            #pragma unroll
            for (int m = 0; m < 8; m++)
                #pragma unroll
                for (int n = 0; n < 8; n++)
                    c[m][n] += a[m] * b[n];
        }
        __syncthreads();
    }

    // epilogue: pd = sqrt(max(sq_i + sq_j - 2*dot, 0)); write tile + mirror
    float sqi[8], sqj[8];
    #pragma unroll
    for (int m = 0; m < 8; m++) sqi[m] = g_sq[bi * 128 + ty * 8 + m];
    #pragma unroll
    for (int n = 0; n < 8; n++) sqj[n] = g_sq[bj * 128 + tx * 8 + n];

    #pragma unroll
    for (int m = 0; m < 8; m++) {
        const int i = bi * 128 + ty * 8 + m;
        #pragma unroll
        for (int n = 0; n < 8; n++) {
            const int j = bj * 128 + tx * 8 + n;
            float d2 = sqi[m] + sqj[n] - 2.f * c[m][n];
            float pd = sqrtf(fmaxf(d2, 0.f));
            g_pd[(size_t)i * BB + j] = pd;
            if (bi != bj) g_pd[(size_t)j * BB + i] = pd;
        }
    }
}

// ---------------- per-row top-10 selection + masked loss ----------------
// Reference: radius = 1-NN distance; w = 1 - clip((pd-radius)/radius,0,1);
// top_k(w,10) == the 10 smallest non-self distances (ranks 1..10), with
// lowest-index tie-break == lexicographic min on (pd_bits, idx).
// NOTE: the rank-1 neighbor IS included (its w = 1 is the max).
__global__ void __launch_bounds__(256) topk_loss_kernel(const int* __restrict__ labels) {
    const int r   = blockIdx.x;
    const int tid = threadIdx.x;

    __shared__ unsigned long long sk[256];
    __shared__ float s_pd[TOPK];
    __shared__ int   s_idx[TOPK];
    __shared__ float s_con[TOPK];

    const float* row = g_pd + (size_t)r * BB;

    // each thread owns 16 keys (coalesced: j = k*256 + tid)
    unsigned long long key[16];
    #pragma unroll
    for (int k = 0; k < 16; k++) {
        int j = k * 256 + tid;
        float pd = row[j];
        key[k] = (j == r) ? 0xFFFFFFFFFFFFFFFFull
                          : (((unsigned long long)__float_as_uint(pd) << 32) |
                             (unsigned)j);
    }

    // 10 rounds of exact lexicographic min (pd, idx); diagonal excluded above.
    for (int sel = 0; sel < TOPK; sel++) {
        unsigned long long loc = 0xFFFFFFFFFFFFFFFFull;
        #pragma unroll
        for (int k = 0; k < 16; k++) loc = min(loc, key[k]);
        sk[tid] = loc;
        __syncthreads();
        for (int s = 128; s > 0; s >>= 1) {
            if (tid < s) sk[tid] = min(sk[tid], sk[tid + s]);
            __syncthreads();
        }
        unsigned long long win = sk[0];
        if (tid == 0) {
            s_pd[sel]  = __uint_as_float((unsigned)(win >> 32));
            s_idx[sel] = (int)(win & 0xFFFFFFFFu);
        }
        #pragma unroll
        for (int k = 0; k < 16; k++)
            if (key[k] == win) key[k] = 0xFFFFFFFFFFFFFFFFull;
        __syncthreads();
    }

    if (tid < TOPK) s_con[tid] = 0.f;
    __syncthreads();

    const float radius = s_pd[0];   // 1-NN distance
    const int wid  = tid >> 5;
    const int lane = tid & 31;

    // 10 neighbor contributions (ranks 1..10), one warp per item
    for (int t = wid; t < TOPK; t += 8) {
        const int   j  = s_idx[t];
        const float pd = s_pd[t];
        float w = 1.f - fminf(fmaxf((pd - radius) / radius, 0.f), 1.f);

        const int lr = labels[r & (NN - 1)];
        const int lj = labels[j & (NN - 1)];
        const bool m = (lr == lj) && (lr != -1) && (lj != -1) &&
                       ((r & (NN - 1)) != (j & (NN - 1)));

        // 128-dim dot of probs rows (float4 per lane)
        const float* pr = g_probs + (size_t)r * CC + lane * 4;
        const float* pj = g_probs + (size_t)j * CC + lane * 4;
        float4 a = *(const float4*)pr;
        float4 b = *(const float4*)pj;
        float s = a.x * b.x + a.y * b.y + a.z * b.z + a.w * b.w;
        #pragma unroll
        for (int off = 16; off > 0; off >>= 1)
            s += __shfl_down_sync(0xffffffffu, s, off);
        if (lane == 0) s_con[t] = m ? (w * s) : 0.f;
    }
    __syncthreads();

    if (tid == 0) {
        float sum = 0.f;
        #pragma unroll
        for (int t = 0; t < TOPK; t++) sum += s_con[t];  // fixed order
        g_partial[r] = sum;
    }
}

// ---------------- deterministic final reduction ----------------
__global__ void __launch_bounds__(1024) finalize_kernel(float* __restrict__ out) {
    __shared__ float sm[1024];
    const int tid = threadIdx.x;
    float s = g_partial[tid] + g_partial[tid + 1024] +
              g_partial[tid + 2048] + g_partial[tid + 3072];
    sm[tid] = s;
    __syncthreads();
    for (int sfx = 512; sfx > 0; sfx >>= 1) {
        if (tid < sfx) sm[tid] += sm[tid + sfx];
        __syncthreads();
    }
    if (tid == 0) out[0] = sm[0] / (float)((size_t)BB * BB);
}

// ---------------- launch ----------------
extern "C" void kernel_launch(void* const* d_in, const int* in_sizes, int n_in,
                              void* d_out, int out_size) {
    const float* zi = (const float*)d_in[0];
    const float* zj = (const float*)d_in[1];
    const float* pi = (const float*)d_in[2];
    const float* pj = (const float*)d_in[3];
    const int*   pl = (const int*)d_in[4];
    float* out = (float*)d_out;

    pack_kernel<<<2048, 512>>>(zi, zj, pi, pj);
    sqnorm_kernel<<<(BB * 32 + 127) / 128, 128>>>();
    dist_gemm_kernel<<<dim3(32, 32), 256>>>();
    topk_loss_kernel<<<BB, 256>>>(pl);
    finalize_kernel<<<1, 1024>>>(out);
}

// round 3
// speedup vs baseline: 1.1045x; 1.1045x over previous
#include <cuda_runtime.h>
#include <cuda_bf16.h>
#include <stdint.h>

#define NN   2048
#define DD   512
#define CC   128
#define BB   4096
#define TOPK 10

// ---------------- device scratch ----------------
__device__ float g_pd[(size_t)BB * BB];    // 64 MB d2 matrix (squared distances)
__device__ float g_feats[(size_t)BB * DD];
__device__ float g_probs[(size_t)BB * CC];
__device__ float g_sq[BB];
__device__ float g_partial[BB];

// ---------------- pack ----------------
__global__ void pack_kernel(const float* __restrict__ zi, const float* __restrict__ zj,
                            const float* __restrict__ pi, const float* __restrict__ pj) {
    const int total_f = NN * DD;
    const int total_p = NN * CC;
    for (int i = blockIdx.x * blockDim.x + threadIdx.x; i < total_f;
         i += gridDim.x * blockDim.x) {
        g_feats[i]           = zi[i];
        g_feats[total_f + i] = zj[i];
        if (i < total_p) {
            g_probs[i]           = pi[i];
            g_probs[total_p + i] = pj[i];
        }
    }
}

// ---------------- row squared norms ----------------
__global__ void sqnorm_kernel() {
    int warp = (blockIdx.x * blockDim.x + threadIdx.x) >> 5;
    int lane = threadIdx.x & 31;
    if (warp >= BB) return;
    const float* row = g_feats + (size_t)warp * DD;
    float s = 0.f;
    #pragma unroll
    for (int q = 0; q < 4; q++) {
        float4 v = *(const float4*)(row + (q * 32 + lane) * 4);
        s += v.x * v.x + v.y * v.y + v.z * v.z + v.w * v.w;
    }
    #pragma unroll
    for (int off = 16; off > 0; off >>= 1)
        s += __shfl_down_sync(0xffffffffu, s, off);
    if (lane == 0) g_sq[warp] = s;
}

// ---------------- symmetric distance GEMM (stores d2, no sqrt) ----------------
// Grid = 528 upper-triangle 128x128 blocks, double-buffered smem.
__global__ void __launch_bounds__(256, 2) dist_gemm_kernel() {
    // decode linear triangular index -> (bi, bj), bi <= bj
    int t = blockIdx.x;
    int bi = 0;
    while (t >= 32 - bi) { t -= 32 - bi; bi++; }
    const int bj = bi + t;

    __shared__ float As[2][8][132];
    __shared__ float Bs[2][8][132];

    const int tid  = threadIdx.x;
    const int tx   = tid & 15;
    const int ty   = tid >> 4;
    const int lrow = tid >> 1;
    const int lk4  = (tid & 1) << 2;

    const float* Ap = g_feats + (size_t)(bi * 128 + lrow) * DD + lk4;
    const float* Bp = g_feats + (size_t)(bj * 128 + lrow) * DD + lk4;

    float c[8][8];
    #pragma unroll
    for (int m = 0; m < 8; m++)
        #pragma unroll
        for (int n = 0; n < 8; n++) c[m][n] = 0.f;

    // preload chunk 0
    {
        float4 av = *(const float4*)(Ap);
        float4 bv = *(const float4*)(Bp);
        As[0][lk4 + 0][lrow] = av.x; As[0][lk4 + 1][lrow] = av.y;
        As[0][lk4 + 2][lrow] = av.z; As[0][lk4 + 3][lrow] = av.w;
        Bs[0][lk4 + 0][lrow] = bv.x; Bs[0][lk4 + 1][lrow] = bv.y;
        Bs[0][lk4 + 2][lrow] = bv.z; Bs[0][lk4 + 3][lrow] = bv.w;
    }
    __syncthreads();

    int buf = 0;
    for (int ch = 1; ch <= DD / 8; ch++) {
        float4 av, bv;
        const bool has = (ch < DD / 8);
        if (has) {
            av = *(const float4*)(Ap + ch * 8);
            bv = *(const float4*)(Bp + ch * 8);
        }
        #pragma unroll
        for (int k = 0; k < 8; k++) {
            float a[8], b[8];
            *(float4*)&a[0] = *(const float4*)&As[buf][k][ty * 8];
            *(float4*)&a[4] = *(const float4*)&As[buf][k][ty * 8 + 4];
            *(float4*)&b[0] = *(const float4*)&Bs[buf][k][tx * 8];
            *(float4*)&b[4] = *(const float4*)&Bs[buf][k][tx * 8 + 4];
            #pragma unroll
            for (int m = 0; m < 8; m++)
                #pragma unroll
                for (int n = 0; n < 8; n++)
                    c[m][n] += a[m] * b[n];
        }
        if (has) {
            const int nb = buf ^ 1;
            As[nb][lk4 + 0][lrow] = av.x; As[nb][lk4 + 1][lrow] = av.y;
            As[nb][lk4 + 2][lrow] = av.z; As[nb][lk4 + 3][lrow] = av.w;
            Bs[nb][lk4 + 0][lrow] = bv.x; Bs[nb][lk4 + 1][lrow] = bv.y;
            Bs[nb][lk4 + 2][lrow] = bv.z; Bs[nb][lk4 + 3][lrow] = bv.w;
        }
        __syncthreads();
        buf ^= 1;
    }

    // epilogue: d2 = sq_i + sq_j - 2*dot (clamp + sqrt deferred to topk)
    float sqi[8], sqj[8];
    #pragma unroll
    for (int m = 0; m < 8; m++) sqi[m] = g_sq[bi * 128 + ty * 8 + m];
    #pragma unroll
    for (int n = 0; n < 8; n++) sqj[n] = g_sq[bj * 128 + tx * 8 + n];

    #pragma unroll
    for (int m = 0; m < 8; m++) {
        const int i = bi * 128 + ty * 8 + m;
        #pragma unroll
        for (int n = 0; n < 8; n++) {
            const int j = bj * 128 + tx * 8 + n;
            const float d2 = fmaf(-2.f, c[m][n], sqi[m] + sqj[n]);
            g_pd[(size_t)i * BB + j] = d2;
            if (bi != bj) g_pd[(size_t)j * BB + i] = d2;
        }
    }
}

// ---------------- per-row top-10 selection + masked loss ----------------
// Select the 10 smallest non-self d2 (lexicographic (d2_bits, idx) = jax
// top_k lowest-index tie-break). sqrt applied only to the 10 winners.
__global__ void __launch_bounds__(256) topk_loss_kernel(const int* __restrict__ labels) {
    const int r    = blockIdx.x;
    const int tid  = threadIdx.x;
    const int lane = tid & 31;
    const int wid  = tid >> 5;

    __shared__ unsigned long long swarp[8];
    __shared__ unsigned long long s_win[TOPK];
    __shared__ float s_con[TOPK];

    const float* row = g_pd + (size_t)r * BB;

    // load 16 keys/thread via 4x float4 (coalesced), cache thread-local min
    unsigned long long key[16];
    unsigned long long loc = 0xFFFFFFFFFFFFFFFFull;
    #pragma unroll
    for (int q = 0; q < 4; q++) {
        const int j0 = q * 1024 + tid * 4;
        float4 v = *(const float4*)(row + j0);
        float d[4] = { fmaxf(v.x, 0.f), fmaxf(v.y, 0.f),
                       fmaxf(v.z, 0.f), fmaxf(v.w, 0.f) };
        #pragma unroll
        for (int e = 0; e < 4; e++) {
            const int j = j0 + e;
            unsigned long long kk =
                (j == r) ? 0xFFFFFFFFFFFFFFFFull
                         : (((unsigned long long)__float_as_uint(d[e]) << 32) |
                            (unsigned)j);
            key[q * 4 + e] = kk;
            loc = min(loc, kk);
        }
    }

    // 10 rounds; keys unique (idx in low bits) so exactly one thread holds win
    for (int sel = 0; sel < TOPK; sel++) {
        unsigned long long w = loc;
        #pragma unroll
        for (int off = 16; off > 0; off >>= 1)
            w = min(w, __shfl_xor_sync(0xffffffffu, w, off));
        if (lane == 0) swarp[wid] = w;
        __syncthreads();
        unsigned long long win = swarp[0];
        #pragma unroll
        for (int i = 1; i < 8; i++) win = min(win, swarp[i]);
        if (tid == 0) s_win[sel] = win;
        if (loc == win) {  // only the owner rescans
            loc = 0xFFFFFFFFFFFFFFFFull;
            #pragma unroll
            for (int k = 0; k < 16; k++) {
                if (key[k] == win) key[k] = 0xFFFFFFFFFFFFFFFFull;
                loc = min(loc, key[k]);
            }
        }
        __syncthreads();
    }

    if (tid < TOPK) s_con[tid] = 0.f;
    __syncthreads();

    const float radius = sqrtf(__uint_as_float((unsigned)(s_win[0] >> 32)));

    // 10 neighbor contributions (ranks 1..10), one warp per item
    for (int t = wid; t < TOPK; t += 8) {
        const unsigned long long win = s_win[t];
        const int   j  = (int)(win & 0xFFFFFFFFu);
        const float pd = sqrtf(__uint_as_float((unsigned)(win >> 32)));
        const float w  = 1.f - fminf(fmaxf((pd - radius) / radius, 0.f), 1.f);

        const int lr = labels[r & (NN - 1)];
        const int lj = labels[j & (NN - 1)];
        const bool m = (lr == lj) && (lr != -1) && (lj != -1) &&
                       ((r & (NN - 1)) != (j & (NN - 1)));

        const float* pr = g_probs + (size_t)r * CC + lane * 4;
        const float* pj = g_probs + (size_t)j * CC + lane * 4;
        float4 a = *(const float4*)pr;
        float4 b = *(const float4*)pj;
        float s = a.x * b.x + a.y * b.y + a.z * b.z + a.w * b.w;
        #pragma unroll
        for (int off = 16; off > 0; off >>= 1)
            s += __shfl_down_sync(0xffffffffu, s, off);
        if (lane == 0) s_con[t] = m ? (w * s) : 0.f;
    }
    __syncthreads();

    if (tid == 0) {
        float sum = 0.f;
        #pragma unroll
        for (int t = 0; t < TOPK; t++) sum += s_con[t];
        g_partial[r] = sum;
    }
}

// ---------------- deterministic final reduction ----------------
__global__ void __launch_bounds__(1024) finalize_kernel(float* __restrict__ out) {
    __shared__ float sm[1024];
    const int tid = threadIdx.x;
    float s = g_partial[tid] + g_partial[tid + 1024] +
              g_partial[tid + 2048] + g_partial[tid + 3072];
    sm[tid] = s;
    __syncthreads();
    for (int sfx = 512; sfx > 0; sfx >>= 1) {
        if (tid < sfx) sm[tid] += sm[tid + sfx];
        __syncthreads();
    }
    if (tid == 0) out[0] = sm[0] / (float)((size_t)BB * BB);
}

// ---------------- launch ----------------
extern "C" void kernel_launch(void* const* d_in, const int* in_sizes, int n_in,
                              void* d_out, int out_size) {
    const float* zi = (const float*)d_in[0];
    const float* zj = (const float*)d_in[1];
    const float* pi = (const float*)d_in[2];
    const float* pj = (const float*)d_in[3];
    const int*   pl = (const int*)d_in[4];
    float* out = (float*)d_out;

    pack_kernel<<<2048, 512>>>(zi, zj, pi, pj);
    sqnorm_kernel<<<(BB * 32 + 127) / 128, 128>>>();
    dist_gemm_kernel<<<528, 256>>>();
    topk_loss_kernel<<<BB, 256>>>(pl);
    finalize_kernel<<<1, 1024>>>(out);
}

// round 5
// speedup vs baseline: 2.2767x; 2.0613x over previous
#include <cuda_runtime.h>
#include <cuda_bf16.h>
#include <stdint.h>

#define NN   2048
#define DD   512
#define CC   128
#define BB   4096
#define TOPK 10

// ---------------- device scratch ----------------
__device__ __align__(16) __nv_bfloat16 g_hi[(size_t)BB * DD];  // 4 MB
__device__ __align__(16) __nv_bfloat16 g_lo[(size_t)BB * DD];  // 4 MB
__device__ __align__(16) float g_pd[(size_t)BB * BB];          // 64 MB d2
__device__ __align__(16) float g_probs[(size_t)BB * CC];
__device__ float g_sq[BB];
__device__ float g_partial[BB];

// ---------------- helpers ----------------
__device__ __forceinline__ uint32_t smem_u32(const void* p) {
    uint32_t a;
    asm("{ .reg .u64 t; cvta.to.shared.u64 t, %1; cvt.u32.u64 %0, t; }"
        : "=r"(a) : "l"(p));
    return a;
}
__device__ __forceinline__ void ldsm4(uint32_t& r0, uint32_t& r1, uint32_t& r2,
                                      uint32_t& r3, uint32_t addr) {
    asm volatile("ldmatrix.sync.aligned.m8n8.x4.shared.b16 {%0,%1,%2,%3}, [%4];"
                 : "=r"(r0), "=r"(r1), "=r"(r2), "=r"(r3) : "r"(addr));
}
__device__ __forceinline__ void mma16816(float* c, const uint32_t* a,
                                         uint32_t b0, uint32_t b1) {
    asm volatile(
        "mma.sync.aligned.m16n8k16.row.col.f32.bf16.bf16.f32 "
        "{%0,%1,%2,%3}, {%4,%5,%6,%7}, {%8,%9}, {%0,%1,%2,%3};"
        : "+f"(c[0]), "+f"(c[1]), "+f"(c[2]), "+f"(c[3])
        : "r"(a[0]), "r"(a[1]), "r"(a[2]), "r"(a[3]), "r"(b0), "r"(b1));
}
#define CP_ASYNC16(dst, src) \
    asm volatile("cp.async.cg.shared.global [%0], [%1], 16;" :: "r"(dst), "l"(src))
#define CP_COMMIT()  asm volatile("cp.async.commit_group;" ::: "memory")
#define CP_WAIT0()   asm volatile("cp.async.wait_group 0;" ::: "memory")

// ---------------- pack: bf16 hi/lo split + probs copy ----------------
__global__ void pack_kernel(const float* __restrict__ zi, const float* __restrict__ zj,
                            const float* __restrict__ pi, const float* __restrict__ pj) {
    const int total_f4 = NN * DD / 4;
    const int total_p4 = NN * CC / 4;
    for (int i4 = blockIdx.x * blockDim.x + threadIdx.x; i4 < total_f4;
         i4 += gridDim.x * blockDim.x) {
        float4 a = ((const float4*)zi)[i4];
        float4 b = ((const float4*)zj)[i4];
        float av[4] = {a.x, a.y, a.z, a.w};
        float bv[4] = {b.x, b.y, b.z, b.w};
        __nv_bfloat16 ah[4], al[4], bh[4], bl[4];
        #pragma unroll
        for (int e = 0; e < 4; e++) {
            ah[e] = __float2bfloat16(av[e]);
            al[e] = __float2bfloat16(av[e] - __bfloat162float(ah[e]));
            bh[e] = __float2bfloat16(bv[e]);
            bl[e] = __float2bfloat16(bv[e] - __bfloat162float(bh[e]));
        }
        __nv_bfloat162* hi2 = (__nv_bfloat162*)g_hi;
        __nv_bfloat162* lo2 = (__nv_bfloat162*)g_lo;
        hi2[2 * i4]     = __nv_bfloat162{ah[0], ah[1]};
        hi2[2 * i4 + 1] = __nv_bfloat162{ah[2], ah[3]};
        lo2[2 * i4]     = __nv_bfloat162{al[0], al[1]};
        lo2[2 * i4 + 1] = __nv_bfloat162{al[2], al[3]};
        const int off = total_f4;
        hi2[2 * (off + i4)]     = __nv_bfloat162{bh[0], bh[1]};
        hi2[2 * (off + i4) + 1] = __nv_bfloat162{bh[2], bh[3]};
        lo2[2 * (off + i4)]     = __nv_bfloat162{bl[0], bl[1]};
        lo2[2 * (off + i4) + 1] = __nv_bfloat162{bl[2], bl[3]};
        if (i4 < total_p4) {
            ((float4*)g_probs)[i4]            = ((const float4*)pi)[i4];
            ((float4*)g_probs)[total_p4 + i4] = ((const float4*)pj)[i4];
        }
    }
}

// ---------------- row squared norms (fp32 originals) ----------------
__global__ void sqnorm_kernel(const float* __restrict__ zi, const float* __restrict__ zj) {
    int warp = (blockIdx.x * blockDim.x + threadIdx.x) >> 5;
    int lane = threadIdx.x & 31;
    if (warp >= BB) return;
    const float* row = (warp < NN) ? (zi + (size_t)warp * DD)
                                   : (zj + (size_t)(warp - NN) * DD);
    float s = 0.f;
    #pragma unroll
    for (int q = 0; q < 4; q++) {
        float4 v = *(const float4*)(row + (q * 32 + lane) * 4);
        s += v.x * v.x + v.y * v.y + v.z * v.z + v.w * v.w;
    }
    #pragma unroll
    for (int off = 16; off > 0; off >>= 1)
        s += __shfl_down_sync(0xffffffffu, s, off);
    if (lane == 0) g_sq[warp] = s;
}

// ---------------- mma.sync distance GEMM ----------------
// 128x128 tile, k-chunk 32, 2-stage cp.async double buffer.
// smem per stage: 4 buffers (Ahi, Alo, Bhi, Blo), each 128 rows x 40 bf16 (80B).
#define BUF_B   10240            // 128 * 80
#define STAGE_B (4 * BUF_B)      // 40960
#define DSMEM_B (2 * STAGE_B)    // 81920 (epilogue reuses: 66048 + 1024 fits)

extern __shared__ char dynsm[];

__global__ void __launch_bounds__(256, 1) dist_gemm_mma() {
    int t = blockIdx.x;
    int bi = 0;
    while (t >= 32 - bi) { t -= 32 - bi; bi++; }
    const int bj = bi + t;

    const int tid  = threadIdx.x;
    const int wid  = tid >> 5;
    const int lane = tid & 31;
    const int wm   = (wid >> 2) * 64;   // warp row offset in tile
    const int wn   = (wid & 3) * 32;    // warp col offset in tile

    const uint32_t sbase = smem_u32(dynsm);

    // per-thread cp.async source/dest (8 x 16B per chunk)
    const __nv_bfloat16* src[8];
    uint32_t dst[8];
    #pragma unroll
    for (int it = 0; it < 8; it++) {
        const int cid = it * 256 + tid;        // 0..2047
        const int b   = cid >> 9;              // 0..3: Ahi, Alo, Bhi, Blo
        const int w   = cid & 511;
        const int row = w >> 2;
        const int seg = w & 3;
        const int grow = ((b < 2) ? bi : bj) * 128 + row;
        src[it] = ((b & 1) ? g_lo : g_hi) + (size_t)grow * DD + seg * 8;
        dst[it] = sbase + b * BUF_B + row * 80 + seg * 16;
    }

    float acc[4][4][4];
    #pragma unroll
    for (int fm = 0; fm < 4; fm++)
        #pragma unroll
        for (int fn = 0; fn < 4; fn++)
            #pragma unroll
            for (int e = 0; e < 4; e++) acc[fm][fn][e] = 0.f;

    // prologue: chunk 0 -> stage 0
    #pragma unroll
    for (int it = 0; it < 8; it++) CP_ASYNC16(dst[it], src[it]);
    CP_COMMIT();

    for (int ch = 0; ch < 16; ch++) {
        CP_WAIT0();
        __syncthreads();
        if (ch < 15) {
            const uint32_t soff = ((ch + 1) & 1) * STAGE_B;
            #pragma unroll
            for (int it = 0; it < 8; it++)
                CP_ASYNC16(dst[it] + soff, src[it] + (ch + 1) * 32);
            CP_COMMIT();
        }
        const uint32_t stg = sbase + (ch & 1) * STAGE_B;

        #pragma unroll
        for (int kst = 0; kst < 2; kst++) {
            const uint32_t ko = kst * 32 + (lane >> 4) * 16;  // k-offset bytes
            uint32_t ahi[4][4], alo[4][4];
            #pragma unroll
            for (int fm = 0; fm < 4; fm++) {
                const uint32_t ra = (wm + fm * 16 + (lane & 15)) * 80 + ko;
                ldsm4(ahi[fm][0], ahi[fm][1], ahi[fm][2], ahi[fm][3], stg + ra);
                ldsm4(alo[fm][0], alo[fm][1], alo[fm][2], alo[fm][3],
                      stg + BUF_B + ra);
            }
            uint32_t bh[2][4], bl[2][4];
            #pragma unroll
            for (int fp = 0; fp < 2; fp++) {
                const uint32_t rb = (wn + fp * 16 + (lane & 15)) * 80 + ko;
                ldsm4(bh[fp][0], bh[fp][1], bh[fp][2], bh[fp][3],
                      stg + 2 * BUF_B + rb);
                ldsm4(bl[fp][0], bl[fp][1], bl[fp][2], bl[fp][3],
                      stg + 3 * BUF_B + rb);
            }
            #pragma unroll
            for (int fm = 0; fm < 4; fm++)
                #pragma unroll
                for (int fn = 0; fn < 4; fn++) {
                    const int fp = fn >> 1, s = fn & 1;
                    mma16816(acc[fm][fn], ahi[fm], bh[fp][s], bh[fp][s + 2]);
                    mma16816(acc[fm][fn], ahi[fm], bl[fp][s], bl[fp][s + 2]);
                    mma16816(acc[fm][fn], alo[fm], bh[fp][s], bh[fp][s + 2]);
                }
        }
        __syncthreads();
    }

    // ---------------- epilogue ----------------
    float* smf = (float*)dynsm;                    // 128 x 129 dots (66048 B)
    float* sqa = (float*)(dynsm + 66048);          // 128 sq_i
    float* sqb = (float*)(dynsm + 66048 + 512);    // 128 sq_j

    if (tid < 128) {
        sqa[tid] = g_sq[bi * 128 + tid];
        sqb[tid] = g_sq[bj * 128 + tid];
    }
    const int grp = lane >> 2, qc = (lane & 3) * 2;
    #pragma unroll
    for (int fm = 0; fm < 4; fm++) {
        const int m0 = wm + fm * 16 + grp;
        #pragma unroll
        for (int fn = 0; fn < 4; fn++) {
            const int n0 = wn + fn * 8 + qc;
            smf[m0 * 129 + n0]           = acc[fm][fn][0];
            smf[m0 * 129 + n0 + 1]       = acc[fm][fn][1];
            smf[(m0 + 8) * 129 + n0]     = acc[fm][fn][2];
            smf[(m0 + 8) * 129 + n0 + 1] = acc[fm][fn][3];
        }
    }
    __syncthreads();

    // direct tile rows (coalesced)
    #pragma unroll
    for (int it = 0; it < 16; it++) {
        const int mr = it * 8 + wid;
        const float si = sqa[mr];
        float4 v;
        v.x = fmaf(-2.f, smf[mr * 129 + lane * 4 + 0], si + sqb[lane * 4 + 0]);
        v.y = fmaf(-2.f, smf[mr * 129 + lane * 4 + 1], si + sqb[lane * 4 + 1]);
        v.z = fmaf(-2.f, smf[mr * 129 + lane * 4 + 2], si + sqb[lane * 4 + 2]);
        v.w = fmaf(-2.f, smf[mr * 129 + lane * 4 + 3], si + sqb[lane * 4 + 3]);
        *(float4*)(g_pd + (size_t)(bi * 128 + mr) * BB + bj * 128 + lane * 4) = v;
    }
    // mirror (transposed smem read, coalesced gmem write)
    if (bi != bj) {
        #pragma unroll
        for (int it = 0; it < 16; it++) {
            const int nr = it * 8 + wid;
            const float sj = sqb[nr];
            float4 v;
            v.x = fmaf(-2.f, smf[(lane * 4 + 0) * 129 + nr], sqa[lane * 4 + 0] + sj);
            v.y = fmaf(-2.f, smf[(lane * 4 + 1) * 129 + nr], sqa[lane * 4 + 1] + sj);
            v.z = fmaf(-2.f, smf[(lane * 4 + 2) * 129 + nr], sqa[lane * 4 + 2] + sj);
            v.w = fmaf(-2.f, smf[(lane * 4 + 3) * 129 + nr], sqa[lane * 4 + 3] + sj);
            *(float4*)(g_pd + (size_t)(bj * 128 + nr) * BB + bi * 128 + lane * 4) = v;
        }
    }
}

// ---------------- per-row top-10 (float domain) + masked loss ----------------
__global__ void __launch_bounds__(256) topk_loss_kernel(const int* __restrict__ labels) {
    const int r    = blockIdx.x;
    const int tid  = threadIdx.x;
    const int lane = tid & 31;
    const int wid  = tid >> 5;
    const float INF = __int_as_float(0x7f800000);

    __shared__ float    swv[2][8];
    __shared__ unsigned swj[2][8];
    __shared__ float s_d[TOPK];
    __shared__ int   s_j[TOPK];
    __shared__ float s_con[TOPK];

    const float* row = g_pd + (size_t)r * BB;

    float v[16];
    #pragma unroll
    for (int q = 0; q < 4; q++) {
        float4 w = ((const float4*)row)[q * 256 + tid];
        v[q * 4 + 0] = w.x; v[q * 4 + 1] = w.y;
        v[q * 4 + 2] = w.z; v[q * 4 + 3] = w.w;
    }
    if (tid == ((r & 1023) >> 2)) v[((r >> 10) << 2) | (r & 3)] = INF;

    float loc = v[0];
    #pragma unroll
    for (int k = 1; k < 16; k++) loc = fminf(loc, v[k]);

    #pragma unroll
    for (int sel = 0; sel < TOPK; sel++) {
        const int p = sel & 1;
        float wm = loc;
        #pragma unroll
        for (int o = 16; o > 0; o >>= 1)
            wm = fminf(wm, __shfl_xor_sync(0xffffffffu, wm, o));
        if (lane == 0) swv[p][wid] = wm;
        __syncthreads();
        float m = swv[p][0];
        #pragma unroll
        for (int i = 1; i < 8; i++) m = fminf(m, swv[p][i]);

        unsigned myj = 0xFFFFFFFFu;
        if (loc == m) {
            #pragma unroll
            for (int k = 0; k < 16; k++)
                if (v[k] == m)
                    myj = min(myj, (unsigned)(((k >> 2) << 10) | (tid << 2) | (k & 3)));
        }
        #pragma unroll
        for (int o = 16; o > 0; o >>= 1)
            myj = min(myj, __shfl_xor_sync(0xffffffffu, myj, o));
        if (lane == 0) swj[p][wid] = myj;
        __syncthreads();
        unsigned jw = swj[p][0];
        #pragma unroll
        for (int i = 1; i < 8; i++) jw = min(jw, swj[p][i]);

        if (tid == 0) { s_d[sel] = m; s_j[sel] = (int)jw; }
        if (tid == ((jw & 1023) >> 2)) {
            v[((jw >> 10) << 2) | (jw & 3)] = INF;
            loc = v[0];
            #pragma unroll
            for (int k = 1; k < 16; k++) loc = fminf(loc, v[k]);
        }
    }
    __syncthreads();

    if (tid < TOPK) s_con[tid] = 0.f;
    __syncthreads();

    const float radius = sqrtf(fmaxf(s_d[0], 0.f));

    for (int t = wid; t < TOPK; t += 8) {
        const int   j  = s_j[t];
        const float pd = sqrtf(fmaxf(s_d[t], 0.f));
        const float w  = 1.f - fminf(fmaxf((pd - radius) / radius, 0.f), 1.f);

        const int lr = labels[r & (NN - 1)];
        const int lj = labels[j & (NN - 1)];
        const bool msk = (lr == lj) && (lr != -1) && (lj != -1) &&
                         ((r & (NN - 1)) != (j & (NN - 1)));

        const float* pr = g_probs + (size_t)r * CC + lane * 4;
        const float* pj = g_probs + (size_t)j * CC + lane * 4;
        float4 a = *(const float4*)pr;
        float4 b = *(const float4*)pj;
        float s = a.x * b.x + a.y * b.y + a.z * b.z + a.w * b.w;
        #pragma unroll
        for (int off = 16; off > 0; off >>= 1)
            s += __shfl_down_sync(0xffffffffu, s, off);
        if (lane == 0) s_con[t] = msk ? (w * s) : 0.f;
    }
    __syncthreads();

    if (tid == 0) {
        float sum = 0.f;
        #pragma unroll
        for (int t = 0; t < TOPK; t++) sum += s_con[t];
        g_partial[r] = sum;
    }
}

// ---------------- deterministic final reduction ----------------
__global__ void __launch_bounds__(1024) finalize_kernel(float* __restrict__ out) {
    __shared__ float sm[1024];
    const int tid = threadIdx.x;
    float s = g_partial[tid] + g_partial[tid + 1024] +
              g_partial[tid + 2048] + g_partial[tid + 3072];
    sm[tid] = s;
    __syncthreads();
    for (int sfx = 512; sfx > 0; sfx >>= 1) {
        if (tid < sfx) sm[tid] += sm[tid + sfx];
        __syncthreads();
    }
    if (tid == 0) out[0] = sm[0] / (float)((size_t)BB * BB);
}

// ---------------- launch ----------------
extern "C" void kernel_launch(void* const* d_in, const int* in_sizes, int n_in,
                              void* d_out, int out_size) {
    const float* zi = (const float*)d_in[0];
    const float* zj = (const float*)d_in[1];
    const float* pi = (const float*)d_in[2];
    const float* pj = (const float*)d_in[3];
    const int*   pl = (const int*)d_in[4];
    float* out = (float*)d_out;

    static int cfg = 0;
    if (!cfg) {
        cudaFuncSetAttribute(dist_gemm_mma,
                             cudaFuncAttributeMaxDynamicSharedMemorySize, DSMEM_B);
        cfg = 1;
    }

    pack_kernel<<<1024, 256>>>(zi, zj, pi, pj);
    sqnorm_kernel<<<(BB * 32 + 127) / 128, 128>>>(zi, zj);
    dist_gemm_mma<<<528, 256, DSMEM_B>>>();
    topk_loss_kernel<<<BB, 256>>>(pl);
    finalize_kernel<<<1, 1024>>>(out);
}